// round 4
// baseline (speedup 1.0000x reference)
#include <cuda_runtime.h>

#define NBATCH  8
#define NCLASS  80
#define NBOX    32
#define NCH     (NBATCH * NCLASS)   // 640
#define THREADS 256
#define NBLOCKS 3840

// Partial-sum scratch: per (b,c) channel, 6 deterministic slots:
// slots 0..3 = the 4 chunks of level0 (128x128), slot 4 = level1 (64x64), slot 5 = level2 (32x32).
// Every slot is written every launch -> no zeroing needed, fully deterministic.
__device__ float g_pos[NCH][6];
__device__ float g_neg[NCH][6];
__device__ int   g_np [NCH][6];
__device__ int   g_arrive;   // zero-initialized; last block resets it -> graph-replay safe

__global__ __launch_bounds__(THREADS) void hough_main(
    const float* __restrict__ h0, const float* __restrict__ h1, const float* __restrict__ h2,
    const float* __restrict__ boxes, const int* __restrict__ labels,
    float* __restrict__ out)
{
    int blk = blockIdx.x;
    const float* heat; int chan, slot, W, logW, base, npix;
    if (blk < 2560)      { heat = h0; chan = blk >> 2; int ck = blk & 3; slot = ck;
                           W = 128; logW = 7; base = ck * 4096; npix = 4096; }
    else if (blk < 3200) { heat = h1; chan = blk - 2560; slot = 4;
                           W = 64;  logW = 6; base = 0;         npix = 4096; }
    else                 { heat = h2; chan = blk - 3200; slot = 5;
                           W = 32;  logW = 5; base = 0;         npix = 1024; }
    int b = chan / NCLASS;
    int c = chan - b * NCLASS;

    // ---- gather boxes of batch b whose label == c (order-independent: used via max only) ----
    __shared__ int   s_cnt;
    __shared__ int   s_x[NBOX], s_y[NBOX], s_r[NBOX];
    __shared__ float s_inv[NBOX];
    if (threadIdx.x == 0) s_cnt = 0;
    __syncthreads();
    if (threadIdx.x < NBOX) {
        int lab = labels[b * NBOX + threadIdx.x];
        if (lab == c) {
            const float* bp = boxes + (size_t)(b * NBOX + threadIdx.x) * 4;
            float Wf = (float)W;
            int x = (int)floorf(bp[0] * Wf);
            int y = (int)floorf(bp[1] * Wf);
            float s2 = bp[2] * Wf + bp[3] * Wf;
            int r = (int)floorf(s2 * 0.25f);      // /4.0 exact as *0.25f
            if (r < 1) r = 1;
            float sigma = (float)(2 * r + 1) * (1.0f / 6.0f);
            int k = atomicAdd(&s_cnt, 1);
            s_x[k] = x; s_y[k] = y; s_r[k] = r;
            s_inv[k] = 1.0f / (2.0f * sigma * sigma);
        }
    }
    __syncthreads();
    int nb = s_cnt;

    const float4* hp = (const float4*)(heat + (size_t)chan * (W * W) + base);
    int nvec = npix >> 2;
    float pacc = 0.f, nacc = 0.f; int npos = 0;

    if (nb == 0) {
        // ---- fast path: no boxes -> target==0 everywhere: loss = log(1-p) * p^2 ----
        for (int f = threadIdx.x; f < nvec; f += THREADS) {
            float4 v = hp[f];
            float hv[4] = {v.x, v.y, v.z, v.w};
            #pragma unroll
            for (int e = 0; e < 4; e++) {
                float h = hv[e];
                float p = __fdividef(1.0f, 1.0f + __expf(-h));
                p = fminf(fmaxf(p, 1e-4f), 1.0f - 1e-4f);
                nacc += __logf(1.0f - p) * (p * p);
            }
        }
    } else {
        // ---- general path: on-the-fly windowed-gaussian scatter-max ----
        for (int f = threadIdx.x; f < nvec; f += THREADS) {
            float4 v = hp[f];
            int pi0 = base + (f << 2);
            float hv[4] = {v.x, v.y, v.z, v.w};
            #pragma unroll
            for (int e = 0; e < 4; e++) {
                int pi = pi0 + e;
                int y = pi >> logW;
                int x = pi & (W - 1);

                float t = 0.f;
                for (int k = 0; k < nb; k++) {
                    int dx = x - s_x[k], dy = y - s_y[k], r = s_r[k];
                    if (dx * dx <= r * r && dy * dy <= r * r) {
                        float d2 = (float)(dx * dx + dy * dy);
                        t = fmaxf(t, __expf(-d2 * s_inv[k]));   // expf(-0.0)==1.0 exactly at center
                    }
                }

                float h = hv[e];
                float p = __fdividef(1.0f, 1.0f + __expf(-h));
                p = fminf(fmaxf(p, 1e-4f), 1.0f - 1e-4f);
                if (t == 1.0f) {
                    float omp = 1.0f - p;
                    pacc += __logf(p) * omp * omp;
                    npos++;
                } else {
                    float omt = 1.0f - t;
                    float w = omt * omt; w *= w;                // (1-t)^4
                    nacc += __logf(1.0f - p) * (p * p) * w;
                }
            }
        }
    }

    // ---- deterministic block reduction ----
    #pragma unroll
    for (int o = 16; o > 0; o >>= 1) {
        pacc += __shfl_down_sync(0xffffffffu, pacc, o);
        nacc += __shfl_down_sync(0xffffffffu, nacc, o);
        npos += __shfl_down_sync(0xffffffffu, npos, o);
    }
    __shared__ float sp[8], sn[8];
    __shared__ int   si[8];
    int wid = threadIdx.x >> 5, lane = threadIdx.x & 31;
    if (lane == 0) { sp[wid] = pacc; sn[wid] = nacc; si[wid] = npos; }
    __syncthreads();

    __shared__ int s_last;
    if (threadIdx.x == 0) {
        float P = 0.f, Ng = 0.f; int I = 0;
        #pragma unroll
        for (int i = 0; i < 8; i++) { P += sp[i]; Ng += sn[i]; I += si[i]; }
        g_pos[chan][slot] = P; g_neg[chan][slot] = Ng; g_np[chan][slot] = I;
        __threadfence();
        int prev = atomicAdd(&g_arrive, 1);
        s_last = (prev == NBLOCKS - 1);
    }
    __syncthreads();

    // ---- last block performs the fused epilogue (fixed-order, deterministic) ----
    if (s_last) {
        float acc = 0.f;
        for (int ch = threadIdx.x; ch < NCH; ch += THREADS) {
            float pl = 0.f, nl = 0.f; int np = 0;
            #pragma unroll
            for (int s = 0; s < 6; s++) {
                pl += __ldcg(&g_pos[ch][s]);
                nl += __ldcg(&g_neg[ch][s]);
                np += __ldcg(&g_np [ch][s]);
            }
            float loss = (np == 0) ? (-nl) : (-(pl + nl) / (float)np);
            acc += fminf(loss, 10.0f);
        }
        #pragma unroll
        for (int o = 16; o > 0; o >>= 1) acc += __shfl_down_sync(0xffffffffu, acc, o);
        __shared__ float sa[8];
        if (lane == 0) sa[wid] = acc;
        __syncthreads();
        if (threadIdx.x == 0) {
            float tot = 0.f;
            #pragma unroll
            for (int i = 0; i < 8; i++) tot += sa[i];
            float mean = tot * (1.0f / (float)NCH);
            float lm = log1pf(mean);
            out[0] = lm / (1.0f + lm);
            g_arrive = 0;   // reset for next graph replay
        }
    }
}

extern "C" void kernel_launch(void* const* d_in, const int* in_sizes, int n_in,
                              void* d_out, int out_size)
{
    const float* h0     = (const float*)d_in[0];   // [8,80,128,128]
    const float* h1     = (const float*)d_in[1];   // [8,80,64,64]
    const float* h2     = (const float*)d_in[2];   // [8,80,32,32]
    const float* boxes  = (const float*)d_in[3];   // [8,32,4]
    const int*   labels = (const int*)d_in[4];     // [8,32]
    // d_in[5] = image_sizes (int64) — cancels mathematically, unused.

    hough_main<<<NBLOCKS, THREADS>>>(h0, h1, h2, boxes, labels, (float*)d_out);
}

// round 5
// speedup vs baseline: 1.3908x; 1.3908x over previous
#include <cuda_runtime.h>

#define NBATCH  8
#define NCLASS  80
#define NBOX    32
#define NCH     (NBATCH * NCLASS)   // 640
#define THREADS 256
#define NBLOCKS 3840
#define LN2f    0.693147180559945f

// Per (b,c) channel, 6 deterministic partial slots:
// slots 0..3 = 4 chunks of level0 (128x128), slot 4 = level1, slot 5 = level2.
// Every slot written every launch -> deterministic, no zeroing needed.
__device__ float g_pos[NCH][6];
__device__ float g_neg[NCH][6];
__device__ int   g_np [NCH][6];
__device__ int   g_arrive;   // zero-init; last block resets -> graph-replay safe

__device__ __forceinline__ float fast_tanh(float x) {
    float y; asm("tanh.approx.f32 %0, %1;" : "=f"(y) : "f"(x)); return y;
}
__device__ __forceinline__ float fast_lg2(float x) {
    float y; asm("lg2.approx.f32 %0, %1;" : "=f"(y) : "f"(x)); return y;
}

// sigmoid via 1 MUFU op, clipped to [1e-4, 1-1e-4] (ref's CLIP; also guards lg2(0))
__device__ __forceinline__ float sigmoid_clip(float h) {
    float p = fmaf(fast_tanh(h * 0.5f), 0.5f, 0.5f);
    return fminf(fmaxf(p, 1e-4f), 1.0f - 1e-4f);
}

// ---- fast path: no boxes in this channel -> target == 0 everywhere ----
template<int NITER>
__device__ __forceinline__ void process_fast(const float4* __restrict__ hp, float& nacc2)
{
    float4 v[NITER];
    #pragma unroll
    for (int i = 0; i < NITER; i++) v[i] = hp[threadIdx.x + i * THREADS];
    #pragma unroll
    for (int i = 0; i < NITER; i++) {
        float hv[4] = {v[i].x, v[i].y, v[i].z, v[i].w};
        #pragma unroll
        for (int e = 0; e < 4; e++) {
            float p = sigmoid_clip(hv[e]);
            nacc2 += fast_lg2(1.0f - p) * (p * p);   // log2-domain; *ln2 once at end
        }
    }
}

// ---- general path: on-the-fly windowed-gaussian scatter-max ----
template<int LOGW, int NITER>
__device__ __forceinline__ void process_box(const float4* __restrict__ hp, int base,
    int nb, const int* __restrict__ s_x, const int* __restrict__ s_y,
    const int* __restrict__ s_r2, const float* __restrict__ s_inv,
    float& pacc2, float& nacc2, int& npos)
{
    float4 v[NITER];
    #pragma unroll
    for (int i = 0; i < NITER; i++) v[i] = hp[threadIdx.x + i * THREADS];
    #pragma unroll
    for (int i = 0; i < NITER; i++) {
        int pi0 = base + ((threadIdx.x + i * THREADS) << 2);
        int y   = pi0 >> LOGW;            // 4 consecutive px share a row at all levels
        int x0  = pi0 & ((1 << LOGW) - 1);
        float hv[4] = {v[i].x, v[i].y, v[i].z, v[i].w};
        float t[4]  = {0.f, 0.f, 0.f, 0.f};
        for (int k = 0; k < nb; k++) {
            int dy  = y - s_y[k];
            int dy2 = dy * dy;
            int r2  = s_r2[k];
            if (dy2 <= r2) {                       // whole-quad row rejection
                float inv = s_inv[k];
                int bx = s_x[k];
                #pragma unroll
                for (int e = 0; e < 4; e++) {
                    int dx  = x0 + e - bx;
                    int dx2 = dx * dx;
                    if (dx2 <= r2) {               // |dx|<=r && |dy|<=r
                        float d2 = (float)(dx2 + dy2);
                        t[e] = fmaxf(t[e], __expf(-d2 * inv));  // expf(-0.0)==1.0 at center
                    }
                }
            }
        }
        #pragma unroll
        for (int e = 0; e < 4; e++) {
            float p = sigmoid_clip(hv[e]);
            if (t[e] == 1.0f) {
                float omp = 1.0f - p;
                pacc2 += fast_lg2(p) * (omp * omp);
                npos++;
            } else {
                float omt = 1.0f - t[e];
                float w = omt * omt; w *= w;       // (1-t)^4
                nacc2 += fast_lg2(1.0f - p) * (p * p) * w;
            }
        }
    }
}

__global__ __launch_bounds__(THREADS) void hough_main(
    const float* __restrict__ h0, const float* __restrict__ h1, const float* __restrict__ h2,
    const float* __restrict__ boxes, const int* __restrict__ labels,
    float* __restrict__ out)
{
    int blk = blockIdx.x;
    const float* heat; int chan, slot, W, base, cat;
    if (blk < 2560)      { heat = h0; chan = blk >> 2; int ck = blk & 3; slot = ck;
                           W = 128; base = ck * 4096; cat = 0; }
    else if (blk < 3200) { heat = h1; chan = blk - 2560; slot = 4; W = 64; base = 0; cat = 1; }
    else                 { heat = h2; chan = blk - 3200; slot = 5; W = 32; base = 0; cat = 2; }
    int b = chan / NCLASS;
    int c = chan - b * NCLASS;

    // ---- gather boxes of batch b with label == c (order-independent: only max uses them) ----
    __shared__ int   s_cnt;
    __shared__ int   s_x[NBOX], s_y[NBOX], s_r2[NBOX];
    __shared__ float s_inv[NBOX];
    if (threadIdx.x == 0) s_cnt = 0;
    __syncthreads();
    if (threadIdx.x < NBOX) {
        int lab = labels[b * NBOX + threadIdx.x];
        if (lab == c) {
            const float* bp = boxes + (size_t)(b * NBOX + threadIdx.x) * 4;
            float Wf = (float)W;
            int x = (int)floorf(bp[0] * Wf);
            int y = (int)floorf(bp[1] * Wf);
            float s2 = bp[2] * Wf + bp[3] * Wf;
            int r = (int)floorf(s2 * 0.25f);       // /4.0 exact as *0.25f
            if (r < 1) r = 1;
            float sigma = (float)(2 * r + 1) * (1.0f / 6.0f);
            int k = atomicAdd(&s_cnt, 1);
            s_x[k] = x; s_y[k] = y; s_r2[k] = r * r;
            s_inv[k] = 1.0f / (2.0f * sigma * sigma);
        }
    }
    __syncthreads();
    int nb = s_cnt;

    const float4* hp = (const float4*)(heat + (size_t)chan * (W * W) + base);
    float pacc2 = 0.f, nacc2 = 0.f; int npos = 0;

    if (nb == 0) {
        if (cat == 2) process_fast<1>(hp, nacc2);
        else          process_fast<4>(hp, nacc2);
    } else {
        if (cat == 0)      process_box<7, 4>(hp, base, nb, s_x, s_y, s_r2, s_inv, pacc2, nacc2, npos);
        else if (cat == 1) process_box<6, 4>(hp, base, nb, s_x, s_y, s_r2, s_inv, pacc2, nacc2, npos);
        else               process_box<5, 1>(hp, base, nb, s_x, s_y, s_r2, s_inv, pacc2, nacc2, npos);
    }

    float pacc = pacc2 * LN2f;   // log2 -> ln, once per thread
    float nacc = nacc2 * LN2f;

    // ---- deterministic block reduction ----
    #pragma unroll
    for (int o = 16; o > 0; o >>= 1) {
        pacc += __shfl_down_sync(0xffffffffu, pacc, o);
        nacc += __shfl_down_sync(0xffffffffu, nacc, o);
        npos += __shfl_down_sync(0xffffffffu, npos, o);
    }
    __shared__ float sp[8], sn[8];
    __shared__ int   si[8];
    int wid = threadIdx.x >> 5, lane = threadIdx.x & 31;
    if (lane == 0) { sp[wid] = pacc; sn[wid] = nacc; si[wid] = npos; }
    __syncthreads();

    __shared__ int s_last;
    if (threadIdx.x == 0) {
        float P = 0.f, Ng = 0.f; int I = 0;
        #pragma unroll
        for (int i = 0; i < 8; i++) { P += sp[i]; Ng += sn[i]; I += si[i]; }
        g_pos[chan][slot] = P; g_neg[chan][slot] = Ng; g_np[chan][slot] = I;
        __threadfence();
        int prev = atomicAdd(&g_arrive, 1);
        s_last = (prev == NBLOCKS - 1);
    }
    __syncthreads();

    // ---- fused epilogue by the last-arriving block (fixed order, deterministic) ----
    if (s_last) {
        float acc = 0.f;
        for (int ch = threadIdx.x; ch < NCH; ch += THREADS) {
            float pl = 0.f, nl = 0.f; int np = 0;
            #pragma unroll
            for (int s = 0; s < 6; s++) {
                pl += __ldcg(&g_pos[ch][s]);
                nl += __ldcg(&g_neg[ch][s]);
                np += __ldcg(&g_np [ch][s]);
            }
            float loss = (np == 0) ? (-nl) : (-(pl + nl) / (float)np);
            acc += fminf(loss, 10.0f);
        }
        #pragma unroll
        for (int o = 16; o > 0; o >>= 1) acc += __shfl_down_sync(0xffffffffu, acc, o);
        __shared__ float sa[8];
        if (lane == 0) sa[wid] = acc;
        __syncthreads();
        if (threadIdx.x == 0) {
            float tot = 0.f;
            #pragma unroll
            for (int i = 0; i < 8; i++) tot += sa[i];
            float mean = tot * (1.0f / (float)NCH);
            float lm = log1pf(mean);
            out[0] = lm / (1.0f + lm);
            g_arrive = 0;   // reset for next graph replay
        }
    }
}

extern "C" void kernel_launch(void* const* d_in, const int* in_sizes, int n_in,
                              void* d_out, int out_size)
{
    const float* h0     = (const float*)d_in[0];   // [8,80,128,128]
    const float* h1     = (const float*)d_in[1];   // [8,80,64,64]
    const float* h2     = (const float*)d_in[2];   // [8,80,32,32]
    const float* boxes  = (const float*)d_in[3];   // [8,32,4]
    const int*   labels = (const int*)d_in[4];     // [8,32]
    // d_in[5] = image_sizes (int64) — cancels mathematically, unused.

    hough_main<<<NBLOCKS, THREADS>>>(h0, h1, h2, boxes, labels, (float*)d_out);
}